// round 4
// baseline (speedup 1.0000x reference)
#include <cuda_runtime.h>
#include <cuda_bf16.h>
#include <math.h>

// Problem constants (from reference): N_CUTS=4e6, DIM=64, N_CLUSTERS=50, N_VARIANTS=2000
#define DIM 64
#define MAX_SEG 100000
#define MAX_CLUSTERS 64

// Scratch for raw segment sums: 100000 * 64 floats = 25.6 MB (static: allocation-free rule)
__device__ float g_raw[(size_t)MAX_SEG * DIM];
__device__ float g_invlib[MAX_CLUSTERS];

__device__ __forceinline__ float4 f4add(float4 a, float4 b) {
    return make_float4(a.x + b.x, a.y + b.y, a.z + b.z, a.w + b.w);
}

// Fast log1p for |x| small (here |x| <~ 0.01 always): 5-term Taylor, error
// x^6/6 (< 3e-9 relative even at x=0.05). Guarded fallback for robustness.
__device__ __forceinline__ float log1p_fast(float x) {
    if (fabsf(x) > 0.1f) return log1pf(x);
    return x * (1.f - x * (0.5f - x * (0.33333333f - x * (0.25f - x * 0.2f))));
}

// ---------------------------------------------------------------------------
// Kernel 1: CSR segment sum, warp-per-segment.
//   lane = h*16 + q : h = row half (0/1), q = float4 index within row.
//   16 rows per warp iteration (8 independent predicated LDG.128 per thread
//   -> MLP=8). Cross-half combine via shfl.down 16; lanes 0..15 store 256B.
// indptr dtype (int32 vs int64) detected inline via ballot on odd words.
// ---------------------------------------------------------------------------
__global__ void __launch_bounds__(256) seg_sum_kernel(
    const float4* __restrict__ emb,   // [n_cuts * 16] float4 (row = 16 float4)
    const int* __restrict__ ipw,      // indptr as 32-bit words
    float* __restrict__ raw,          // [n_seg * 64]
    int n_seg)
{
    const int lane = threadIdx.x & 31;
    const int wid  = threadIdx.x >> 5;
    const int s    = blockIdx.x * 8 + wid;
    if (s >= n_seg) return;

    const unsigned odd_nonzero =
        __ballot_sync(0xffffffffu, ipw[2 * lane + 1] != 0);
    long long r0, r1;
    if (odd_nonzero == 0u) {  // int64
        const long long* ip = (const long long*)ipw;
        r0 = __ldg(&ip[s]); r1 = __ldg(&ip[s + 1]);
    } else {                   // int32
        r0 = (long long)__ldg(&ipw[s]); r1 = (long long)__ldg(&ipw[s + 1]);
    }

    const int q = lane & 15;
    const int h = lane >> 4;

    float4 acc0 = make_float4(0.f, 0.f, 0.f, 0.f);
    float4 acc1 = acc0, acc2 = acc0, acc3 = acc0;
    float4 acc4 = acc0, acc5 = acc0, acc6 = acc0, acc7 = acc0;
    const float4 zero = acc0;

    // rows r+h+2j for j=0..7 per iteration; stride 16 rows
    for (long long r = r0 + h; r < r1; r += 16) {
        const float4* p = emb + r * 16 + q;
        float4 v0 = __ldg(p);
        float4 v1 = (r +  2 < r1) ? __ldg(p +  32) : zero;
        float4 v2 = (r +  4 < r1) ? __ldg(p +  64) : zero;
        float4 v3 = (r +  6 < r1) ? __ldg(p +  96) : zero;
        float4 v4 = (r +  8 < r1) ? __ldg(p + 128) : zero;
        float4 v5 = (r + 10 < r1) ? __ldg(p + 160) : zero;
        float4 v6 = (r + 12 < r1) ? __ldg(p + 192) : zero;
        float4 v7 = (r + 14 < r1) ? __ldg(p + 224) : zero;
        acc0 = f4add(acc0, v0); acc1 = f4add(acc1, v1);
        acc2 = f4add(acc2, v2); acc3 = f4add(acc3, v3);
        acc4 = f4add(acc4, v4); acc5 = f4add(acc5, v5);
        acc6 = f4add(acc6, v6); acc7 = f4add(acc7, v7);
    }

    float4 acc = f4add(f4add(f4add(acc0, acc1), f4add(acc2, acc3)),
                       f4add(f4add(acc4, acc5), f4add(acc6, acc7)));
    acc.x += __shfl_down_sync(0xffffffffu, acc.x, 16);
    acc.y += __shfl_down_sync(0xffffffffu, acc.y, 16);
    acc.z += __shfl_down_sync(0xffffffffu, acc.z, 16);
    acc.w += __shfl_down_sync(0xffffffffu, acc.w, 16);

    if (h == 0) {
        ((float4*)(raw + (long long)s * DIM))[q] = acc;
    }
}

// ---------------------------------------------------------------------------
// Kernel 1b: precompute 1/lib once (removes 12.8M MUFU.RCP from finalize)
// ---------------------------------------------------------------------------
__global__ void inv_lib_kernel(const float* __restrict__ lib, int n_clusters)
{
    int t = threadIdx.x;
    if (t < n_clusters) g_invlib[t] = 1.f / lib[t];
}

// ---------------------------------------------------------------------------
// Kernel 2: per-(variant, dim) normalization across clusters.
//   y = log1p(raw * invlib[c]) ; mean/std (ddof=1) over clusters on UNSHIFTED
//   y (shift-invariance avoids fp32 cancellation from the -2 offset).
//   out[.., :64] = y - 2 ; out[.., 64:] = (y - mean)/(std + 1e-5)
// Taylor log1p -> pure FMA; two passes over c, second pass L2-hot.
// ---------------------------------------------------------------------------
__global__ void __launch_bounds__(256) finalize_kernel(
    const float* __restrict__ raw,   // [n_clusters * n_variants * 64]
    float* __restrict__ out,         // [n_clusters * n_variants * 128]
    int n_clusters, int n_variants)
{
    const int idx = blockIdx.x * blockDim.x + threadIdx.x; // v*64 + d
    const int total = n_variants * DIM;
    if (idx >= total) return;

    const int v = idx >> 6;
    const int d = idx & 63;

    const long long base = (long long)v * DIM + d;
    const long long cstride = (long long)n_variants * DIM;

    float sum = 0.f, ssq = 0.f;
    #pragma unroll 5
    for (int c = 0; c < n_clusters; ++c) {
        float y = log1p_fast(__ldg(&raw[base + (long long)c * cstride]) * g_invlib[c]);
        sum += y;
        ssq = fmaf(y, y, ssq);
    }

    const float meanY = sum / (float)n_clusters;
    const float var = (ssq - sum * meanY) / (float)(n_clusters - 1);
    const float stdv = sqrtf(fmaxf(var, 0.f));
    const float inv_denom = 1.f / (stdv + 1e-5f);

    #pragma unroll 5
    for (int c = 0; c < n_clusters; ++c) {
        float y = log1p_fast(__ldg(&raw[base + (long long)c * cstride]) * g_invlib[c]);
        long long o = ((long long)c * n_variants + v) * (2 * DIM);
        out[o + d] = y - 2.0f;
        out[o + DIM + d] = (y - meanY) * inv_denom;
    }
}

extern "C" void kernel_launch(void* const* d_in, const int* in_sizes, int n_in,
                              void* d_out, int out_size)
{
    const float* emb    = (const float*)d_in[0];   // [n_cuts, 64] fp32
    const float* lib    = (const float*)d_in[1];   // [n_clusters] fp32
    const int*   indptr = (const int*)d_in[2];     // [n_seg + 1] int32 OR int64 words

    const int n_clusters = in_sizes[1];
    const int n_seg      = in_sizes[2] - 1;
    const int n_variants = n_seg / n_clusters;

    float* raw;
    cudaGetSymbolAddress((void**)&raw, g_raw);

    // Kernel 1: one warp per segment, 8 warps per block
    const int blocks1 = (n_seg + 7) / 8;
    seg_sum_kernel<<<blocks1, 256>>>((const float4*)emb, indptr, raw, n_seg);

    // Kernel 1b: reciprocals of lib (independent of kernel 1; tiny)
    inv_lib_kernel<<<1, 64>>>(lib, n_clusters);

    // Kernel 2: one thread per (variant, dim)
    const int total = n_variants * DIM;
    const int threads = 256;
    const int blocks2 = (total + threads - 1) / threads;
    finalize_kernel<<<blocks2, threads>>>(raw, (float*)d_out,
                                          n_clusters, n_variants);
}

// round 5
// speedup vs baseline: 1.8466x; 1.8466x over previous
#include <cuda_runtime.h>
#include <cuda_bf16.h>
#include <math.h>

// Problem constants (from reference): N_CUTS=4e6, DIM=64, N_CLUSTERS=50, N_VARIANTS=2000
#define DIM 64
#define MAX_SEG 100000
#define MAX_CLUSTERS 64

// Scratch for raw segment sums: 100000 * 64 floats = 25.6 MB (static: allocation-free rule)
__device__ float g_raw[(size_t)MAX_SEG * DIM];

__device__ __forceinline__ float4 f4add(float4 a, float4 b) {
    return make_float4(a.x + b.x, a.y + b.y, a.z + b.z, a.w + b.w);
}

// Fast log1p for |x| small (here |x| <~ 0.01 always): 5-term Taylor, error
// x^6/6 (< 3e-9 relative even at x=0.05). Guarded fallback for robustness.
__device__ __forceinline__ float log1p_fast(float x) {
    if (fabsf(x) > 0.1f) return log1pf(x);
    return x * (1.f - x * (0.5f - x * (0.33333333f - x * (0.25f - x * 0.2f))));
}

// Inline indptr dtype check: int64 values here are << 2^31, so every odd
// 32-bit word is zero; int32 odd words are sorted random breakpoints
// (essentially never all zero). Reads only the first 128B (L1-hot).
__device__ __forceinline__ bool indptr_is_64(const int* __restrict__ ipw) {
    int nz = 0;
    #pragma unroll
    for (int k = 1; k < 32; k += 2) nz |= ipw[k];
    return nz == 0;
}

// ---------------------------------------------------------------------------
// Kernel 1: CSR segment sum. One CTA per segment (block-per-segment won R2's
// bake-off: 100k small CTAs retire independently, so exponentially-long
// segments don't hold 8 siblings hostage the way warp-per-segment blocks do).
// 128 threads = 8 rows in flight x 16 float4 lanes; each iteration streams a
// contiguous 2KB block fully coalesced. smem tree-reduce over row groups.
// ---------------------------------------------------------------------------
__global__ void __launch_bounds__(128) seg_sum_kernel(
    const float4* __restrict__ emb,   // [n_cuts * 16] float4 (row = 16 float4)
    const int* __restrict__ ipw,      // indptr as 32-bit words
    float* __restrict__ raw)          // [n_seg * 64]
{
    const int s = blockIdx.x;
    long long r0, r1;
    if (indptr_is_64(ipw)) {
        const long long* ip = (const long long*)ipw;
        r0 = __ldg(&ip[s]); r1 = __ldg(&ip[s + 1]);
    } else {
        r0 = (long long)__ldg(&ipw[s]); r1 = (long long)__ldg(&ipw[s + 1]);
    }

    const int tid = threadIdx.x;
    const int q = tid & 15;   // float4 index within a row (0..15)
    const int g = tid >> 4;   // row group (0..7)

    float ax = 0.f, ay = 0.f, az = 0.f, aw = 0.f;
    for (long long r = r0 + g; r < r1; r += 8) {
        float4 v = __ldg(&emb[r * 16 + q]);
        ax += v.x; ay += v.y; az += v.z; aw += v.w;
    }

    __shared__ float4 sm[128];
    sm[tid] = make_float4(ax, ay, az, aw);
    __syncthreads();

    #pragma unroll
    for (int st = 64; st >= 16; st >>= 1) {
        if (tid < st) {
            float4 a = sm[tid];
            float4 b = sm[tid + st];
            sm[tid] = make_float4(a.x + b.x, a.y + b.y, a.z + b.z, a.w + b.w);
        }
        __syncthreads();
    }

    if (tid < 16) {
        ((float4*)(raw + (long long)s * DIM))[tid] = sm[tid];
    }
}

// ---------------------------------------------------------------------------
// Kernel 2: per-(variant, dim) normalization across clusters.
//   y = log1p(raw / lib[c]) ; mean/std (ddof=1) over clusters on UNSHIFTED y
//   (shift-invariance avoids fp32 cancellation from the -2 offset).
//   out[.., :64] = y - 2 ; out[.., 64:] = (y - mean)/(std + 1e-5)
// Taylor log1p -> pure FMA. 1/lib computed once per block into shared memory
// (50 RCPs/block, trivial) instead of 12.8M MUFU.RCP. Two passes over c,
// second pass L2-hot (25.6 MB << 126 MB L2).
// ---------------------------------------------------------------------------
__global__ void __launch_bounds__(256) finalize_kernel(
    const float* __restrict__ raw,   // [n_clusters * n_variants * 64]
    const float* __restrict__ lib,   // [n_clusters]
    float* __restrict__ out,         // [n_clusters * n_variants * 128]
    int n_clusters, int n_variants)
{
    __shared__ float s_inv[MAX_CLUSTERS];
    if (threadIdx.x < n_clusters) s_inv[threadIdx.x] = 1.f / lib[threadIdx.x];
    __syncthreads();

    const int idx = blockIdx.x * blockDim.x + threadIdx.x; // v*64 + d
    const int total = n_variants * DIM;
    if (idx >= total) return;

    const int v = idx >> 6;
    const int d = idx & 63;

    const long long base = (long long)v * DIM + d;
    const long long cstride = (long long)n_variants * DIM;

    float sum = 0.f, ssq = 0.f;
    #pragma unroll 5
    for (int c = 0; c < n_clusters; ++c) {
        float y = log1p_fast(__ldg(&raw[base + (long long)c * cstride]) * s_inv[c]);
        sum += y;
        ssq = fmaf(y, y, ssq);
    }

    const float meanY = sum / (float)n_clusters;
    const float var = (ssq - sum * meanY) / (float)(n_clusters - 1);
    const float stdv = sqrtf(fmaxf(var, 0.f));
    const float inv_denom = 1.f / (stdv + 1e-5f);

    #pragma unroll 5
    for (int c = 0; c < n_clusters; ++c) {
        float y = log1p_fast(__ldg(&raw[base + (long long)c * cstride]) * s_inv[c]);
        long long o = ((long long)c * n_variants + v) * (2 * DIM);
        out[o + d] = y - 2.0f;
        out[o + DIM + d] = (y - meanY) * inv_denom;
    }
}

extern "C" void kernel_launch(void* const* d_in, const int* in_sizes, int n_in,
                              void* d_out, int out_size)
{
    const float* emb    = (const float*)d_in[0];   // [n_cuts, 64] fp32
    const float* lib    = (const float*)d_in[1];   // [n_clusters] fp32
    const int*   indptr = (const int*)d_in[2];     // [n_seg + 1] int32 OR int64 words

    const int n_clusters = in_sizes[1];
    const int n_seg      = in_sizes[2] - 1;
    const int n_variants = n_seg / n_clusters;

    float* raw;
    cudaGetSymbolAddress((void**)&raw, g_raw);

    // Kernel 1: one block per segment
    seg_sum_kernel<<<n_seg, 128>>>((const float4*)emb, indptr, raw);

    // Kernel 2: one thread per (variant, dim)
    const int total = n_variants * DIM;
    const int threads = 256;
    const int blocks2 = (total + threads - 1) / threads;
    finalize_kernel<<<blocks2, threads>>>(raw, lib, (float*)d_out,
                                          n_clusters, n_variants);
}

// round 6
// speedup vs baseline: 1.8653x; 1.0101x over previous
#include <cuda_runtime.h>
#include <cuda_bf16.h>
#include <math.h>

// Problem constants (from reference): N_CUTS=4e6, DIM=64, N_CLUSTERS=50, N_VARIANTS=2000
#define DIM 64
#define MAX_SEG 100000
#define MAX_CLUSTERS 64

// Scratch for raw segment sums: 100000 * 64 floats = 25.6 MB (static: allocation-free rule)
__device__ float g_raw[(size_t)MAX_SEG * DIM];

// Fast log1p for |x| small (here |x| <~ 0.01 always): 5-term Taylor, error
// x^6/6 (< 3e-9 relative even at x=0.05). Guarded fallback for robustness.
__device__ __forceinline__ float log1p_fast(float x) {
    if (fabsf(x) > 0.1f) return log1pf(x);
    return x * (1.f - x * (0.5f - x * (0.33333333f - x * (0.25f - x * 0.2f))));
}

// Inline indptr dtype check: int64 values here are << 2^31, so every odd
// 32-bit word is zero; int32 odd words are sorted random breakpoints
// (essentially never all zero). Reads only the first 128B (L1-hot).
__device__ __forceinline__ bool indptr_is_64(const int* __restrict__ ipw) {
    int nz = 0;
    #pragma unroll
    for (int k = 1; k < 32; k += 2) nz |= ipw[k];
    return nz == 0;
}

// ---------------------------------------------------------------------------
// Kernel 1: CSR segment sum. One CTA per segment (block-per-segment: 100k
// small CTAs retire independently -> fine-grained load balance across the
// exponential segment-length distribution). 128 threads = 8 rows x 16 float4
// lanes. 2-deep predicated unroll (rows g and g+8, stride 16) -> 2
// independent LDG.128 outstanding per thread without changing structure.
// ---------------------------------------------------------------------------
__global__ void __launch_bounds__(128) seg_sum_kernel(
    const float4* __restrict__ emb,   // [n_cuts * 16] float4 (row = 16 float4)
    const int* __restrict__ ipw,      // indptr as 32-bit words
    float* __restrict__ raw)          // [n_seg * 64]
{
    const int s = blockIdx.x;
    long long r0, r1;
    if (indptr_is_64(ipw)) {
        const long long* ip = (const long long*)ipw;
        r0 = __ldg(&ip[s]); r1 = __ldg(&ip[s + 1]);
    } else {
        r0 = (long long)__ldg(&ipw[s]); r1 = (long long)__ldg(&ipw[s + 1]);
    }

    const int tid = threadIdx.x;
    const int q = tid & 15;   // float4 index within a row (0..15)
    const int g = tid >> 4;   // row group (0..7)

    float4 a0 = make_float4(0.f, 0.f, 0.f, 0.f);
    float4 a1 = a0;
    const float4 zero = a0;

    for (long long r = r0 + g; r < r1; r += 16) {
        const float4* p = emb + r * 16 + q;
        float4 v0 = __ldg(p);                                  // row r
        float4 v1 = (r + 8 < r1) ? __ldg(p + 128) : zero;      // row r+8
        a0.x += v0.x; a0.y += v0.y; a0.z += v0.z; a0.w += v0.w;
        a1.x += v1.x; a1.y += v1.y; a1.z += v1.z; a1.w += v1.w;
    }
    a0.x += a1.x; a0.y += a1.y; a0.z += a1.z; a0.w += a1.w;

    __shared__ float4 sm[128];
    sm[tid] = a0;
    __syncthreads();

    #pragma unroll
    for (int st = 64; st >= 16; st >>= 1) {
        if (tid < st) {
            float4 a = sm[tid];
            float4 b = sm[tid + st];
            sm[tid] = make_float4(a.x + b.x, a.y + b.y, a.z + b.z, a.w + b.w);
        }
        __syncthreads();
    }

    if (tid < 16) {
        ((float4*)(raw + (long long)s * DIM))[tid] = sm[tid];
    }
}

// ---------------------------------------------------------------------------
// Kernel 2: per-(variant, dim) normalization across clusters.
//   y = log1p(raw / lib[c]) ; mean/std (ddof=1) over clusters on UNSHIFTED y
//   (shift-invariance avoids fp32 cancellation from the -2 offset).
//   out[.., :64] = y - 2 ; out[.., 64:] = (y - mean)/(std + 1e-5)
// Taylor log1p -> pure FMA; 1/lib once per block into smem. All indexing
// 32-bit (max offset 12.8M << 2^31) to kill 64-bit IMAD address chains.
// Two passes over c; second pass L2-hot (25.6 MB << 126 MB L2).
// ---------------------------------------------------------------------------
__global__ void __launch_bounds__(256) finalize_kernel(
    const float* __restrict__ raw,   // [n_clusters * n_variants * 64]
    const float* __restrict__ lib,   // [n_clusters]
    float* __restrict__ out,         // [n_clusters * n_variants * 128]
    int n_clusters, int n_variants)
{
    __shared__ float s_inv[MAX_CLUSTERS];
    if (threadIdx.x < n_clusters) s_inv[threadIdx.x] = 1.f / lib[threadIdx.x];
    __syncthreads();

    const int idx = blockIdx.x * blockDim.x + threadIdx.x; // v*64 + d
    const int total = n_variants * DIM;
    if (idx >= total) return;

    const int v = idx >> 6;
    const int d = idx & 63;

    const int cstride = n_variants * DIM;      // 128000
    const float* p = raw + idx;                // raw[base + c*cstride]

    float sum = 0.f, ssq = 0.f;
    #pragma unroll 5
    for (int c = 0; c < n_clusters; ++c) {
        float y = log1p_fast(__ldg(p) * s_inv[c]);
        p += cstride;
        sum += y;
        ssq = fmaf(y, y, ssq);
    }

    const float meanY = sum / (float)n_clusters;
    const float var = (ssq - sum * meanY) / (float)(n_clusters - 1);
    const float stdv = sqrtf(fmaxf(var, 0.f));
    const float inv_denom = 1.f / (stdv + 1e-5f);

    const float* p2 = raw + idx;
    float* o = out + v * (2 * DIM) + d;        // out[(c*nv + v)*128 + d]
    const int ostride = n_variants * 2 * DIM;  // 256000
    #pragma unroll 5
    for (int c = 0; c < n_clusters; ++c) {
        float y = log1p_fast(__ldg(p2) * s_inv[c]);
        p2 += cstride;
        o[0]   = y - 2.0f;
        o[DIM] = (y - meanY) * inv_denom;
        o += ostride;
    }
}

extern "C" void kernel_launch(void* const* d_in, const int* in_sizes, int n_in,
                              void* d_out, int out_size)
{
    const float* emb    = (const float*)d_in[0];   // [n_cuts, 64] fp32
    const float* lib    = (const float*)d_in[1];   // [n_clusters] fp32
    const int*   indptr = (const int*)d_in[2];     // [n_seg + 1] int32 OR int64 words

    const int n_clusters = in_sizes[1];
    const int n_seg      = in_sizes[2] - 1;
    const int n_variants = n_seg / n_clusters;

    float* raw;
    cudaGetSymbolAddress((void**)&raw, g_raw);

    // Kernel 1: one block per segment
    seg_sum_kernel<<<n_seg, 128>>>((const float4*)emb, indptr, raw);

    // Kernel 2: one thread per (variant, dim)
    const int total = n_variants * DIM;
    const int threads = 256;
    const int blocks2 = (total + threads - 1) / threads;
    finalize_kernel<<<blocks2, threads>>>(raw, lib, (float*)d_out,
                                          n_clusters, n_variants);
}